// round 17
// baseline (speedup 1.0000x reference)
#include <cuda_runtime.h>
#include <cuda_fp16.h>
#include <math.h>
#include <stdint.h>

#define BB 16
#define SS 1024
#define EE 768
#define HH 12
#define DD 64
#define FF 3072
#define ROWS (BB * SS)
#define QKV_N (3 * EE)

// scratch
__device__ __half g_ah[ROWS * EE];
__device__ __half g_fh[ROWS * FF];
__device__ __half g_qkvh[ROWS * QKV_N];   // qkv; later reused as fp16 f2 buffer
__device__ __half g_wqkvt[QKV_N * EE];
__device__ __half g_wpt[EE * EE];
__device__ __half g_w1t[FF * EE];
__device__ __half g_w2t[EE * FF];
__device__ float g_bqkv[QKV_N];
__device__ float g_x1[ROWS * EE];

__device__ __forceinline__ uint32_t swz(uint32_t o) { return o ^ ((o >> 3) & 0x70); }
__device__ __forceinline__ uint32_t pack2(float x, float y) {
    __half2 t = __floats2half2_rn(x, y);
    return *(uint32_t*)&t;
}

// ---------------- weight prep (tiled, coalesced) ----------------
__global__ void pack_wqkv_tiled(const float* __restrict__ Wq, const float* __restrict__ Wk,
                                const float* __restrict__ Wv) {
    __shared__ float t[32][33];
    int z = blockIdx.z, sec = z / 12, h = z % 12;
    const float* W = (sec == 0) ? Wq : (sec == 1) ? Wk : Wv;
    float sc = (sec == 0) ? 0.125f : 1.0f;
    int d0 = blockIdx.x * 32, e0 = blockIdx.y * 32;
    int tx = threadIdx.x, ty = threadIdx.y;
#pragma unroll
    for (int j = ty; j < 32; j += 8)
        t[j][tx] = W[((size_t)h * EE + e0 + j) * DD + d0 + tx] * sc;
    __syncthreads();
#pragma unroll
    for (int j = ty; j < 32; j += 8)
        g_wqkvt[(size_t)(sec * 768 + h * 64 + d0 + j) * EE + e0 + tx] =
            __float2half_rn(t[tx][j]);
}

__global__ void pack_bias_kernel(const float* __restrict__ bq, const float* __restrict__ bk,
                                 const float* __restrict__ bv) {
    int idx = blockIdx.x * blockDim.x + threadIdx.x;
    if (idx >= QKV_N) return;
    int sec = idx / 768;
    const float* bsrc = (sec == 0) ? bq : (sec == 1) ? bk : bv;
    float v = bsrc[idx % 768];
    g_bqkv[idx] = (sec == 0) ? v * 0.125f : v;
}

__global__ void transpose_h_tiled(const float* __restrict__ in,
                                  __half* __restrict__ oh, int K, int N) {
    __shared__ float t[32][33];
    int n0 = blockIdx.x * 32, k0 = blockIdx.y * 32;
    int tx = threadIdx.x, ty = threadIdx.y;
#pragma unroll
    for (int j = ty; j < 32; j += 8)
        t[j][tx] = in[(size_t)(k0 + j) * N + n0 + tx];
    __syncthreads();
#pragma unroll
    for (int j = ty; j < 32; j += 8)
        oh[(size_t)(n0 + j) * K + k0 + tx] = __float2half_rn(t[tx][j]);
}

// ---------------- LN: warp-per-row, 8 rows/block ----------------
__device__ __forceinline__ float wsum(float v) {
#pragma unroll
    for (int m = 16; m; m >>= 1) v += __shfl_xor_sync(0xffffffffu, v, m);
    return v;
}

__global__ void __launch_bounds__(256) ln_h_kernel(const float* __restrict__ in,
                                                   const float* __restrict__ gam,
                                                   const float* __restrict__ bet,
                                                   __half* __restrict__ oh) {
    int w = threadIdx.x >> 5, lane = threadIdx.x & 31;
    size_t row = (size_t)blockIdx.x * 8 + w;
    const float4* xp = (const float4*)(in + row * EE);
    float4 xv[6];
    float s = 0.f;
#pragma unroll
    for (int i = 0; i < 6; i++) {
        xv[i] = xp[lane + 32 * i];
        s += xv[i].x + xv[i].y + xv[i].z + xv[i].w;
    }
    float mu = wsum(s) * (1.f / EE);
    float v = 0.f;
#pragma unroll
    for (int i = 0; i < 6; i++) {
        xv[i].x -= mu; xv[i].y -= mu; xv[i].z -= mu; xv[i].w -= mu;
        v += xv[i].x * xv[i].x + xv[i].y * xv[i].y + xv[i].z * xv[i].z + xv[i].w * xv[i].w;
    }
    float rstd = rsqrtf(wsum(v) * (1.f / EE) + 1e-5f);
    uint2* op = (uint2*)(oh + row * EE);
#pragma unroll
    for (int i = 0; i < 6; i++) {
        float4 g = __ldg(&((const float4*)gam)[lane + 32 * i]);
        float4 be = __ldg(&((const float4*)bet)[lane + 32 * i]);
        uint2 o;
        o.x = pack2(xv[i].x * rstd * g.x + be.x, xv[i].y * rstd * g.y + be.y);
        o.y = pack2(xv[i].z * rstd * g.z + be.z, xv[i].w * rstd * g.w + be.w);
        op[lane + 32 * i] = o;
    }
}

// final LN: fp16 input (f2), fp32 residual, fp32 out
__global__ void __launch_bounds__(256) ln_final_kernel(const __half* __restrict__ in,
                                                       const float* __restrict__ gam,
                                                       const float* __restrict__ bet,
                                                       const float* __restrict__ res,
                                                       float* __restrict__ out) {
    int w = threadIdx.x >> 5, lane = threadIdx.x & 31;
    size_t row = (size_t)blockIdx.x * 8 + w;
    const uint2* xp = (const uint2*)(in + row * EE);
    float4 xv[6];
    float s = 0.f;
#pragma unroll
    for (int i = 0; i < 6; i++) {
        uint2 p = xp[lane + 32 * i];
        __half2 h0 = *(__half2*)&p.x, h1 = *(__half2*)&p.y;
        float2 f0 = __half22float2(h0), f1 = __half22float2(h1);
        xv[i] = make_float4(f0.x, f0.y, f1.x, f1.y);
        s += xv[i].x + xv[i].y + xv[i].z + xv[i].w;
    }
    float mu = wsum(s) * (1.f / EE);
    float v = 0.f;
#pragma unroll
    for (int i = 0; i < 6; i++) {
        xv[i].x -= mu; xv[i].y -= mu; xv[i].z -= mu; xv[i].w -= mu;
        v += xv[i].x * xv[i].x + xv[i].y * xv[i].y + xv[i].z * xv[i].z + xv[i].w * xv[i].w;
    }
    float rstd = rsqrtf(wsum(v) * (1.f / EE) + 1e-5f);
    float4* op = (float4*)(out + row * EE);
    const float4* rp = (const float4*)(res + row * EE);
#pragma unroll
    for (int i = 0; i < 6; i++) {
        float4 g = __ldg(&((const float4*)gam)[lane + 32 * i]);
        float4 be = __ldg(&((const float4*)bet)[lane + 32 * i]);
        float4 r = rp[lane + 32 * i];
        float4 o;
        o.x = xv[i].x * rstd * g.x + be.x + r.x;
        o.y = xv[i].y * rstd * g.y + be.y + r.y;
        o.z = xv[i].z * rstd * g.z + be.z + r.z;
        o.w = xv[i].w * rstd * g.w + be.w + r.w;
        op[lane + 32 * i] = o;
    }
}

// ---------------- HMMA primitives (fp16) ----------------
__device__ __forceinline__ void cpasync16(uint32_t dst, const void* src) {
    asm volatile("cp.async.cg.shared.global [%0], [%1], 16;" :: "r"(dst), "l"(src));
}
__device__ __forceinline__ void ldm4(uint32_t* r, uint32_t addr) {
    asm volatile("ldmatrix.sync.aligned.m8n8.x4.shared.b16 {%0,%1,%2,%3}, [%4];"
                 : "=r"(r[0]), "=r"(r[1]), "=r"(r[2]), "=r"(r[3]) : "r"(addr));
}
__device__ __forceinline__ void ldm4t(uint32_t* r, uint32_t addr) {
    asm volatile("ldmatrix.sync.aligned.m8n8.x4.trans.shared.b16 {%0,%1,%2,%3}, [%4];"
                 : "=r"(r[0]), "=r"(r[1]), "=r"(r[2]), "=r"(r[3]) : "r"(addr));
}
__device__ __forceinline__ void mma16816(float* d, const uint32_t* a, uint32_t b0, uint32_t b1) {
    asm volatile(
        "mma.sync.aligned.m16n8k16.row.col.f32.f16.f16.f32 "
        "{%0,%1,%2,%3}, {%4,%5,%6,%7}, {%8,%9}, {%0,%1,%2,%3};"
        : "+f"(d[0]), "+f"(d[1]), "+f"(d[2]), "+f"(d[3])
        : "r"(a[0]), "r"(a[1]), "r"(a[2]), "r"(a[3]), "r"(b0), "r"(b1));
}

// ---------------- HMMA GEMM: 128x128 CTA, 128 thr, 64x64 warp, 3-stage ------
// Register double-buffered fragments; frag loads precede next-stage cp.async.
// 2 CTAs/SM. EPI: 0 bias->f32, 1 bias+gelu->fp16, 2 bias+res->f32, 3 bias->fp16
#define STG 32768

template <int EPI>
__global__ void __launch_bounds__(128, 2) tcgemm(const __half* __restrict__ Ah,
                                                 const __half* __restrict__ Bh,
                                                 const float* __restrict__ bias,
                                                 const float* __restrict__ res,
                                                 float* __restrict__ C,
                                                 __half* __restrict__ Ch,
                                                 int N, int K) {
    extern __shared__ char sm[];
    uint32_t sbase = (uint32_t)__cvta_generic_to_shared(sm);
    int tid = threadIdx.x;
    int lane = tid & 31, w = tid >> 5;
    int wm = w >> 1, wn = w & 1;
    int bn = blockIdx.x * 128, bm = blockIdx.y * 128;

    float acc[4][8][4];
#pragma unroll
    for (int i = 0; i < 4; i++)
#pragma unroll
        for (int j = 0; j < 8; j++)
#pragma unroll
            for (int q = 0; q < 4; q++) acc[i][j][q] = 0.f;

    int nk = K >> 6;

#define LOAD_STAGE(kc, buf)                                                        \
    {                                                                              \
        uint32_t sb_ = sbase + (buf) * STG;                                        \
        _Pragma("unroll")                                                          \
        for (int ii = 0; ii < 16; ii++) {                                          \
            int i = tid + ii * 128;                                                \
            int t = i >> 10, wrd = i & 1023, r = wrd >> 3, c = wrd & 7;            \
            int rb = t ? bn : bm;                                                  \
            const __half* sp = (t ? Bh : Ah) + (size_t)(rb + r) * K + (kc) * 64 + c * 8; \
            cpasync16(sb_ + t * 16384 + swz(r * 128 + c * 16), sp);                \
        }                                                                          \
        asm volatile("cp.async.commit_group;" ::: "memory");                       \
    }

#define LOAD_FRAGS(sb, ks, p)                                                      \
    {                                                                              \
        _Pragma("unroll")                                                          \
        for (int mt = 0; mt < 4; mt++) {                                           \
            int row = wm * 64 + mt * 16 + ra;                                      \
            ldm4(Af[p][mt], (sb) + swz(row * 128 + ((ks) * 16 + ka) * 2));         \
        }                                                                          \
        _Pragma("unroll")                                                          \
        for (int pr = 0; pr < 4; pr++) {                                           \
            int row = wn * 64 + pr * 16 + rb_n;                                    \
            ldm4(Bf[p][pr], (sb) + 16384 + swz(row * 128 + ((ks) * 16 + kb_n) * 2)); \
        }                                                                          \
    }

    LOAD_STAGE(0, 0);
    LOAD_STAGE(1, 1);

    int ra = (lane & 7) + ((lane & 8) ? 8 : 0);
    int ka = (lane & 16) ? 8 : 0;
    int rb_n = (lane & 7) + ((lane & 16) ? 8 : 0);
    int kb_n = (lane & 8) ? 8 : 0;

    uint32_t Af[2][4][4], Bf[2][4][4];
    int buf = 0;
    for (int kc = 0; kc < nk; kc++) {
        if (kc + 1 < nk) {
            asm volatile("cp.async.wait_group 1;" ::: "memory");
        } else {
            asm volatile("cp.async.wait_group 0;" ::: "memory");
        }
        __syncthreads();
        uint32_t sb = sbase + buf * STG;
        LOAD_FRAGS(sb, 0, 0);          // critical path first
        if (kc + 2 < nk) {             // then bulk prefetch (independent)
            int nb = buf + 2;
            if (nb >= 3) nb -= 3;
            LOAD_STAGE(kc + 2, nb);
        }
#pragma unroll
        for (int ks = 0; ks < 4; ks++) {
            int cur = ks & 1;
            if (ks < 3) LOAD_FRAGS(sb, ks + 1, cur ^ 1);
#pragma unroll
            for (int mt = 0; mt < 4; mt++)
#pragma unroll
                for (int nt = 0; nt < 8; nt++) {
                    int pr = nt >> 1, o = (nt & 1) * 2;
                    mma16816(acc[mt][nt], Af[cur][mt], Bf[cur][pr][o], Bf[cur][pr][o + 1]);
                }
        }
        if (++buf == 3) buf = 0;
    }

    int l4 = lane >> 2, l2 = (lane & 3) * 2;
#pragma unroll
    for (int mt = 0; mt < 4; mt++)
#pragma unroll
        for (int nt = 0; nt < 8; nt++) {
            int col = bn + wn * 64 + nt * 8 + l2;
            float b0 = __ldg(&bias[col]), b1 = __ldg(&bias[col + 1]);
#pragma unroll
            for (int half = 0; half < 2; half++) {
                size_t row = (size_t)(bm + wm * 64 + mt * 16 + l4 + half * 8);
                float v0 = acc[mt][nt][half * 2 + 0] + b0;
                float v1 = acc[mt][nt][half * 2 + 1] + b1;
                if (EPI == 2) {
                    float2 rr = __ldg((const float2*)&res[row * N + col]);
                    v0 += rr.x;
                    v1 += rr.y;
                }
                if (EPI == 1) {
                    v0 = 0.5f * v0 * (1.0f + erff(v0 * 0.70710678118654752f));
                    v1 = 0.5f * v1 * (1.0f + erff(v1 * 0.70710678118654752f));
                }
                if (EPI == 1 || EPI == 3) {
                    *(__half2*)&Ch[row * N + col] = __floats2half2_rn(v0, v1);
                } else {
                    *(float2*)&C[row * N + col] = make_float2(v0, v1);
                }
            }
        }
#undef LOAD_FRAGS
#undef LOAD_STAGE
}

// ---------------- HMMA flash attention: 128-row Q tile, Q frags hoisted ------
__global__ void __launch_bounds__(256, 2) attn_kernel(const __half* __restrict__ qkvh,
                                                      __half* __restrict__ oh) {
    extern __shared__ char smc[];
    uint32_t sb = (uint32_t)__cvta_generic_to_shared(smc);
    uint32_t Qs = sb;

    int qt = gridDim.x - 1 - blockIdx.x;   // heavy (large qt) first
    int bh = blockIdx.y;
    int b = bh / HH, h = bh % HH;
    int tid = threadIdx.x, lane = tid & 31, w = tid >> 5;
    size_t base = (size_t)b * SS * QKV_N;
    int hoff = h * DD;

#pragma unroll
    for (int ii = 0; ii < 4; ii++) {
        int i = tid + ii * 256;
        int r = i >> 3, c = i & 7;
        cpasync16(Qs + swz(r * 128 + c * 16),
                  qkvh + base + (size_t)(qt * 128 + r) * QKV_N + hoff + c * 8);
    }

#define ISSUE_KV(kt, bufo)                                                          \
    {                                                                               \
        _Pragma("unroll")                                                           \
        for (int ii = 0; ii < 4; ii++) {                                            \
            int i = tid + ii * 256;                                                 \
            int ts = i >> 9, wrd = i & 511, r = wrd >> 3, c = wrd & 7;              \
            cpasync16(sb + (bufo) + ts * 8192 + swz(r * 128 + c * 16),              \
                      qkvh + base + (size_t)((kt) * 64 + r) * QKV_N + hoff +        \
                          (ts ? 2 * EE : EE) + c * 8);                              \
        }                                                                           \
        asm volatile("cp.async.commit_group;" ::: "memory");                        \
    }

    ISSUE_KV(0, 16384);   // Q cp.asyncs are committed in this same group

    int ra = (lane & 7) + ((lane & 8) ? 8 : 0);
    int ka = (lane & 16) ? 8 : 0;
    int rbn = (lane & 7) + ((lane & 16) ? 8 : 0);
    int kbn = (lane & 8) ? 8 : 0;
    int vkr = (lane & 7) + ((lane & 8) ? 8 : 0);
    int vnc = (lane & 16) ? 8 : 0;
    int r0 = lane >> 2, c0 = (lane & 3) * 2;

    int qrow = qt * 128 + w * 16;
    int ktmax = 2 * qt + 1;

    // wait for Q + KV0, then load Q fragments ONCE (kt-invariant)
    asm volatile("cp.async.wait_group 0;" ::: "memory");
    __syncthreads();
    uint32_t qf[4][4];
#pragma unroll
    for (int kc = 0; kc < 4; kc++)
        ldm4(qf[kc], Qs + swz((w * 16 + ra) * 128 + (kc * 16 + ka) * 2));

    float m0 = -1e30f, m1 = -1e30f, l0 = 0.f, l1 = 0.f;
    float o[8][4];
#pragma unroll
    for (int i = 0; i < 8; i++)
#pragma unroll
        for (int j = 0; j < 4; j++) o[i][j] = 0.f;

    for (int kt = 0; kt <= ktmax; kt++) {
        if (kt > 0) {
            asm volatile("cp.async.wait_group 0;" ::: "memory");
            __syncthreads();   // KV kt visible; all warps done with buffer (kt+1)&1
        }
        uint32_t kvo = 16384 + (kt & 1) * 16384;
        if (kt < ktmax) ISSUE_KV(kt + 1, 16384 + ((kt + 1) & 1) * 16384);
        uint32_t Kh = sb + kvo, Vh = sb + kvo + 8192;

        if (kt * 64 <= qrow + 15) {
            float s[8][4];
#pragma unroll
            for (int i = 0; i < 8; i++)
#pragma unroll
                for (int j = 0; j < 4; j++) s[i][j] = 0.f;
#pragma unroll
            for (int kc = 0; kc < 4; kc++) {
                uint32_t kh[4][4];
#pragma unroll
                for (int tg = 0; tg < 4; tg++)
                    ldm4(kh[tg], Kh + swz((tg * 16 + rbn) * 128 + (kc * 16 + kbn) * 2));
#pragma unroll
                for (int nt = 0; nt < 8; nt++) {
                    int pr = nt >> 1, oo = (nt & 1) * 2;
                    mma16816(s[nt], qf[kc], kh[pr][oo], kh[pr][oo + 1]);
                }
            }

            if (kt * 64 + 63 > qrow) {
                int row0 = qrow + r0, row1 = row0 + 8;
#pragma unroll
                for (int nt = 0; nt < 8; nt++) {
                    int c = kt * 64 + nt * 8 + c0;
                    if (c > row0) s[nt][0] = -1e30f;
                    if (c + 1 > row0) s[nt][1] = -1e30f;
                    if (c > row1) s[nt][2] = -1e30f;
                    if (c + 1 > row1) s[nt][3] = -1e30f;
                }
            }

            float mt0 = -1e30f, mt1 = -1e30f;
#pragma unroll
            for (int nt = 0; nt < 8; nt++) {
                mt0 = fmaxf(mt0, fmaxf(s[nt][0], s[nt][1]));
                mt1 = fmaxf(mt1, fmaxf(s[nt][2], s[nt][3]));
            }
#pragma unroll
            for (int off = 1; off <= 2; off <<= 1) {
                mt0 = fmaxf(mt0, __shfl_xor_sync(0xffffffffu, mt0, off));
                mt1 = fmaxf(mt1, __shfl_xor_sync(0xffffffffu, mt1, off));
            }
            float mn0 = fmaxf(m0, mt0), mn1 = fmaxf(m1, mt1);
            float sc0 = __expf(m0 - mn0), sc1 = __expf(m1 - mn1);
            float rs0 = 0.f, rs1 = 0.f;
#pragma unroll
            for (int nt = 0; nt < 8; nt++) {
                s[nt][0] = __expf(s[nt][0] - mn0);
                s[nt][1] = __expf(s[nt][1] - mn0);
                s[nt][2] = __expf(s[nt][2] - mn1);
                s[nt][3] = __expf(s[nt][3] - mn1);
                rs0 += s[nt][0] + s[nt][1];
                rs1 += s[nt][2] + s[nt][3];
            }
#pragma unroll
            for (int off = 1; off <= 2; off <<= 1) {
                rs0 += __shfl_xor_sync(0xffffffffu, rs0, off);
                rs1 += __shfl_xor_sync(0xffffffffu, rs1, off);
            }
            l0 = l0 * sc0 + rs0;
            l1 = l1 * sc1 + rs1;
            m0 = mn0;
            m1 = mn1;
#pragma unroll
            for (int i = 0; i < 8; i++) {
                o[i][0] *= sc0; o[i][1] *= sc0;
                o[i][2] *= sc1; o[i][3] *= sc1;
            }

#pragma unroll
            for (int kc = 0; kc < 4; kc++) {
                uint32_t aph[4];
                aph[0] = pack2(s[2 * kc][0], s[2 * kc][1]);
                aph[1] = pack2(s[2 * kc][2], s[2 * kc][3]);
                aph[2] = pack2(s[2 * kc + 1][0], s[2 * kc + 1][1]);
                aph[3] = pack2(s[2 * kc + 1][2], s[2 * kc + 1][3]);
                uint32_t vh[4][4];
#pragma unroll
                for (int dg = 0; dg < 4; dg++)
                    ldm4t(vh[dg], Vh + swz((kc * 16 + vkr) * 128 + (dg * 16 + vnc) * 2));
#pragma unroll
                for (int dt = 0; dt < 8; dt++) {
                    int pr = dt >> 1, oo = (dt & 1) * 2;
                    mma16816(o[dt], aph, vh[pr][oo], vh[pr][oo + 1]);
                }
            }
        }
    }

    float inv0 = 1.f / l0, inv1 = 1.f / l1;
    size_t row0 = (size_t)b * SS + qrow + r0;
    size_t row1 = row0 + 8;
#pragma unroll
    for (int dt = 0; dt < 8; dt++) {
        int d = hoff + dt * 8 + c0;
        *(__half2*)&oh[row0 * EE + d] = __floats2half2_rn(o[dt][0] * inv0, o[dt][1] * inv0);
        *(__half2*)&oh[row1 * EE + d] = __floats2half2_rn(o[dt][2] * inv1, o[dt][3] * inv1);
    }
#undef ISSUE_KV
}

// ---------------- launch ----------------
extern "C" void kernel_launch(void* const* d_in, const int* in_sizes, int n_in,
                              void* d_out, int out_size) {
    const float* x = (const float*)d_in[0];
    const float* Wq = (const float*)d_in[1];
    const float* bq = (const float*)d_in[2];
    const float* Wk = (const float*)d_in[3];
    const float* bk = (const float*)d_in[4];
    const float* Wv = (const float*)d_in[5];
    const float* bv = (const float*)d_in[6];
    const float* Wp = (const float*)d_in[7];
    const float* bp = (const float*)d_in[8];
    const float* ln1_g = (const float*)d_in[9];
    const float* ln1_b = (const float*)d_in[10];
    const float* ln2_g = (const float*)d_in[11];
    const float* ln2_b = (const float*)d_in[12];
    const float* W1 = (const float*)d_in[13];
    const float* b1 = (const float*)d_in[14];
    const float* W2 = (const float*)d_in[15];
    const float* b2 = (const float*)d_in[16];
    const float* lnf_g = (const float*)d_in[17];
    const float* lnf_b = (const float*)d_in[18];
    float* out = (float*)d_out;

    __half *p_ah, *p_fh, *p_qkvh, *p_wq, *p_wp, *p_w1, *p_w2;
    float *p_bqkv, *p_x1;
    cudaGetSymbolAddress((void**)&p_ah, g_ah);
    cudaGetSymbolAddress((void**)&p_fh, g_fh);
    cudaGetSymbolAddress((void**)&p_qkvh, g_qkvh);
    cudaGetSymbolAddress((void**)&p_wq, g_wqkvt);
    cudaGetSymbolAddress((void**)&p_wp, g_wpt);
    cudaGetSymbolAddress((void**)&p_w1, g_w1t);
    cudaGetSymbolAddress((void**)&p_w2, g_w2t);
    cudaGetSymbolAddress((void**)&p_bqkv, g_bqkv);
    cudaGetSymbolAddress((void**)&p_x1, g_x1);
    __half* p_f2h = p_qkvh;   // reuse qkv storage (dead after attention) for fp16 f2

    int gsmem = 3 * STG;  // 98304
    cudaFuncSetAttribute(tcgemm<0>, cudaFuncAttributeMaxDynamicSharedMemorySize, gsmem);
    cudaFuncSetAttribute(tcgemm<1>, cudaFuncAttributeMaxDynamicSharedMemorySize, gsmem);
    cudaFuncSetAttribute(tcgemm<2>, cudaFuncAttributeMaxDynamicSharedMemorySize, gsmem);
    cudaFuncSetAttribute(tcgemm<3>, cudaFuncAttributeMaxDynamicSharedMemorySize, gsmem);
    int asmem = 49152;
    cudaFuncSetAttribute(attn_kernel, cudaFuncAttributeMaxDynamicSharedMemorySize, asmem);

    dim3 tb(32, 8);
    pack_wqkv_tiled<<<dim3(2, 24, 36), tb>>>(Wq, Wk, Wv);
    pack_bias_kernel<<<9, 256>>>(bq, bk, bv);
    transpose_h_tiled<<<dim3(EE / 32, EE / 32), tb>>>(Wp, p_wp, EE, EE);
    transpose_h_tiled<<<dim3(FF / 32, EE / 32), tb>>>(W1, p_w1, EE, FF);
    transpose_h_tiled<<<dim3(EE / 32, FF / 32), tb>>>(W2, p_w2, FF, EE);

    ln_h_kernel<<<ROWS / 8, 256>>>(x, ln1_g, ln1_b, p_ah);
    tcgemm<3><<<dim3(QKV_N / 128, ROWS / 128), 128, gsmem>>>(
        p_ah, p_wq, p_bqkv, nullptr, nullptr, p_qkvh, QKV_N, EE);
    attn_kernel<<<dim3(SS / 128, BB * HH), 256, asmem>>>(p_qkvh, p_ah);
    tcgemm<2><<<dim3(EE / 128, ROWS / 128), 128, gsmem>>>(
        p_ah, p_wp, bp, x, p_x1, nullptr, EE, EE);
    ln_h_kernel<<<ROWS / 8, 256>>>(p_x1, ln2_g, ln2_b, p_ah);
    tcgemm<1><<<dim3(FF / 128, ROWS / 128), 128, gsmem>>>(
        p_ah, p_w1, b1, nullptr, nullptr, p_fh, FF, EE);
    tcgemm<3><<<dim3(EE / 128, ROWS / 128), 128, gsmem>>>(
        p_fh, p_w2, b2, nullptr, nullptr, p_f2h, EE, FF);
    ln_final_kernel<<<ROWS / 8, 256>>>(p_f2h, lnf_g, lnf_b, p_x1, out);
}